// round 1
// baseline (speedup 1.0000x reference)
#include <cuda_runtime.h>
#include <math.h>

// Problem constants (fixed by setup_inputs)
#define BB 8
#define MM 4096
#define EE 2048
#define DD 128

#define NODE_ELEMS (BB*MM*DD)   // 4,194,304
#define EDGE_ELEMS (BB*EE*DD)   // 2,097,152

// Scratch (device globals; no allocation allowed)
__device__ float g_att [NODE_ELEMS];   // feat @ Wa^T
__device__ float g_eatt[EDGE_ELEMS];   // inc^T @ att
__device__ float g_agg [EDGE_ELEMS];   // inc^T @ feat
__device__ float g_pre [EDGE_ELEMS];   // agg * softmax_e(eatt)
__device__ float g_w   [NODE_ELEMS];   // inc @ ef

// ---------------------------------------------------------------------------
// Shared 128x128x16 tile MMA core: 256 threads, 8x8 per thread
// ---------------------------------------------------------------------------
__device__ __forceinline__ void mma_tile(const float (*As)[128],
                                         const float (*Bs)[128],
                                         float acc[8][8], int tx, int ty) {
#pragma unroll
    for (int k = 0; k < 16; k++) {
        float a[8], b[8];
        *(float4*)(a)     = *(const float4*)&As[k][ty * 8];
        *(float4*)(a + 4) = *(const float4*)&As[k][ty * 8 + 4];
        *(float4*)(b)     = *(const float4*)&Bs[k][tx * 8];
        *(float4*)(b + 4) = *(const float4*)&Bs[k][tx * 8 + 4];
#pragma unroll
        for (int i = 0; i < 8; i++)
#pragma unroll
            for (int j = 0; j < 8; j++)
                acc[i][j] = fmaf(a[i], b[j], acc[i][j]);
    }
}

__device__ __forceinline__ void store_tile(float* __restrict__ C, size_t ld,
                                           size_t r0, int c0,
                                           const float acc[8][8], int tx, int ty) {
#pragma unroll
    for (int i = 0; i < 8; i++) {
        float* crow = C + (r0 + (size_t)(ty * 8 + i)) * ld + c0 + tx * 8;
        *(float4*)crow       = make_float4(acc[i][0], acc[i][1], acc[i][2], acc[i][3]);
        *(float4*)(crow + 4) = make_float4(acc[i][4], acc[i][5], acc[i][6], acc[i][7]);
    }
}

// ---------------------------------------------------------------------------
// Kernel: C[r, j] = sum_k X[r,k] * W[j,k]    (X: [R,128] row-major, W: [128,128])
// grid.x = R/128
// ---------------------------------------------------------------------------
__global__ __launch_bounds__(256)
void gemm_xwt(const float* __restrict__ X, const float* __restrict__ W,
              float* __restrict__ C) {
    __shared__ float As[16][128];
    __shared__ float Bs[16][128];
    const int tid = threadIdx.x;
    const int tx = tid & 15, ty = tid >> 4;
    const size_t r0 = (size_t)blockIdx.x * 128;

    float acc[8][8];
#pragma unroll
    for (int i = 0; i < 8; i++)
#pragma unroll
        for (int j = 0; j < 8; j++) acc[i][j] = 0.0f;

    for (int k0 = 0; k0 < 128; k0 += 16) {
#pragma unroll
        for (int l = 0; l < 2; l++) {
            int q = tid * 2 + l;        // 0..511
            int row = q >> 2, kq = q & 3;
            float4 va = *(const float4*)(X + (r0 + row) * 128 + k0 + kq * 4);
            As[kq * 4 + 0][row] = va.x; As[kq * 4 + 1][row] = va.y;
            As[kq * 4 + 2][row] = va.z; As[kq * 4 + 3][row] = va.w;
            float4 vb = *(const float4*)(W + (size_t)row * 128 + k0 + kq * 4);
            Bs[kq * 4 + 0][row] = vb.x; Bs[kq * 4 + 1][row] = vb.y;
            Bs[kq * 4 + 2][row] = vb.z; Bs[kq * 4 + 3][row] = vb.w;
        }
        __syncthreads();
        mma_tile(As, Bs, acc, tx, ty);
        __syncthreads();
    }
    store_tile(C, 128, r0, 0, acc, tx, ty);
}

// ---------------------------------------------------------------------------
// Kernel: C[b,e,d] = sum_m inc[b,m,e] * X[b,m,d]   (A^T GEMM, K = M = 4096)
// blockIdx.y selects (att -> eatt) or (feat -> agg). grid: (E/128, 2, B)
// ---------------------------------------------------------------------------
__global__ __launch_bounds__(256)
void gemm_incT(const float* __restrict__ inc, const float* __restrict__ att,
               const float* __restrict__ feat,
               float* __restrict__ eatt, float* __restrict__ agg) {
    __shared__ float As[16][128];
    __shared__ float Bs[16][128];
    const int tid = threadIdx.x;
    const int tx = tid & 15, ty = tid >> 4;
    const int b = blockIdx.z;
    const float* A  = inc + (size_t)b * MM * EE;                       // [M,E]
    const float* Xb = (blockIdx.y ? feat : att) + (size_t)b * MM * DD; // [M,D]
    float* Cb = (blockIdx.y ? agg : eatt) + (size_t)b * EE * DD;       // [E,D]
    const int e0 = blockIdx.x * 128;

    float acc[8][8];
#pragma unroll
    for (int i = 0; i < 8; i++)
#pragma unroll
        for (int j = 0; j < 8; j++) acc[i][j] = 0.0f;

    for (int k0 = 0; k0 < MM; k0 += 16) {
#pragma unroll
        for (int l = 0; l < 2; l++) {
            int q = tid * 2 + l;        // 0..511
            int kr = q >> 5, iq = q & 31;
            *(float4*)&As[kr][iq * 4] =
                *(const float4*)(A + (size_t)(k0 + kr) * EE + e0 + iq * 4);
            *(float4*)&Bs[kr][iq * 4] =
                *(const float4*)(Xb + (size_t)(k0 + kr) * DD + iq * 4);
        }
        __syncthreads();
        mma_tile(As, Bs, acc, tx, ty);
        __syncthreads();
    }
    store_tile(Cb, DD, e0, 0, acc, tx, ty);
}

// ---------------------------------------------------------------------------
// Kernel: w[b,m,d] = sum_e inc[b,m,e] * ef[b,e,d]   (K = E = 2048)
// grid: (M/128, 1, B)
// ---------------------------------------------------------------------------
__global__ __launch_bounds__(256)
void gemm_incE(const float* __restrict__ inc, const float* __restrict__ ef,
               float* __restrict__ w) {
    __shared__ float As[16][128];
    __shared__ float Bs[16][128];
    const int tid = threadIdx.x;
    const int tx = tid & 15, ty = tid >> 4;
    const int b = blockIdx.z;
    const float* A  = inc + (size_t)b * MM * EE;   // [M,E]
    const float* Bf = ef  + (size_t)b * EE * DD;   // [E,D]
    float* Cb = w + (size_t)b * MM * DD;
    const int m0 = blockIdx.x * 128;

    float acc[8][8];
#pragma unroll
    for (int i = 0; i < 8; i++)
#pragma unroll
        for (int j = 0; j < 8; j++) acc[i][j] = 0.0f;

    for (int k0 = 0; k0 < EE; k0 += 16) {
#pragma unroll
        for (int l = 0; l < 2; l++) {
            int q = tid * 2 + l;
            // A tile (transpose on load): As[k][i] = inc[(m0+i), k0+k]
            int row = q >> 2, kq = q & 3;
            float4 va = *(const float4*)(A + (size_t)(m0 + row) * EE + k0 + kq * 4);
            As[kq * 4 + 0][row] = va.x; As[kq * 4 + 1][row] = va.y;
            As[kq * 4 + 2][row] = va.z; As[kq * 4 + 3][row] = va.w;
            // B tile direct: Bs[k][j] = ef[(k0+k), j]
            int kr = q >> 5, jq = q & 31;
            *(float4*)&Bs[kr][jq * 4] =
                *(const float4*)(Bf + (size_t)(k0 + kr) * DD + jq * 4);
        }
        __syncthreads();
        mma_tile(As, Bs, acc, tx, ty);
        __syncthreads();
    }
    store_tile(Cb, DD, m0, 0, acc, tx, ty);
}

// ---------------------------------------------------------------------------
// Kernel: pre[b,e,d] = agg[b,e,d] * softmax over e of eatt[b,:,d]
// grid: (D/32, B), block: (32, 8)
// ---------------------------------------------------------------------------
__global__ __launch_bounds__(256)
void softmax_mul(const float* __restrict__ eatt, const float* __restrict__ agg,
                 float* __restrict__ pre) {
    const int b = blockIdx.y;
    const int d = blockIdx.x * 32 + threadIdx.x;
    const int ey = threadIdx.y;
    const float* Eb = eatt + (size_t)b * EE * DD;
    const float* Ab = agg  + (size_t)b * EE * DD;
    float* Pb = pre + (size_t)b * EE * DD;

    __shared__ float rmax[8][32];
    __shared__ float rsum[8][32];

    float mx = -3.0e38f;
    for (int e = ey; e < EE; e += 8)
        mx = fmaxf(mx, Eb[(size_t)e * DD + d]);
    rmax[ey][threadIdx.x] = mx;
    __syncthreads();
    float m = rmax[0][threadIdx.x];
#pragma unroll
    for (int i = 1; i < 8; i++) m = fmaxf(m, rmax[i][threadIdx.x]);

    float s = 0.0f;
    for (int e = ey; e < EE; e += 8)
        s += expf(Eb[(size_t)e * DD + d] - m);
    rsum[ey][threadIdx.x] = s;
    __syncthreads();
    float sum = 0.0f;
#pragma unroll
    for (int i = 0; i < 8; i++) sum += rsum[i][threadIdx.x];
    const float inv = 1.0f / sum;

    for (int e = ey; e < EE; e += 8) {
        size_t idx = (size_t)e * DD + d;
        Pb[idx] = Ab[idx] * expf(Eb[idx] - m) * inv;
    }
}

// ---------------------------------------------------------------------------
// Launch. Mathematical note: the n_layers recurrence is a fixed point
// (ef_{k+1} = a*ef_k + (1-a)*ef_base with ef_1 = ef_base), so outputs equal
// the single-pass base values for any n_layers >= 1 and any alpha. ec_Wa is
// dead code in the reference. So we compute exactly one pass.
// ---------------------------------------------------------------------------
extern "C" void kernel_launch(void* const* d_in, const int* in_sizes, int n_in,
                              void* d_out, int out_size) {
    const float* features = (const float*)d_in[0];
    const float* inc      = (const float*)d_in[1];
    const float* vc_Wa    = (const float*)d_in[2];
    const float* vc_Wp    = (const float*)d_in[3];
    const float* ec_Wp    = (const float*)d_in[6];

    float* out_node = (float*)d_out;                 // [B,M,D]
    float* out_edge = out_node + NODE_ELEMS;         // [B,E,D]

    float *p_att, *p_eatt, *p_agg, *p_pre, *p_w;
    cudaGetSymbolAddress((void**)&p_att,  g_att);
    cudaGetSymbolAddress((void**)&p_eatt, g_eatt);
    cudaGetSymbolAddress((void**)&p_agg,  g_agg);
    cudaGetSymbolAddress((void**)&p_pre,  g_pre);
    cudaGetSymbolAddress((void**)&p_w,    g_w);

    // 1. att = feat @ vc_Wa^T             [B*M, D]
    gemm_xwt<<<(BB * MM) / 128, 256>>>(features, vc_Wa, p_att);

    // 2. eatt = inc^T @ att ; agg = inc^T @ feat     [B, E, D]
    gemm_incT<<<dim3(EE / 128, 2, BB), 256>>>(inc, p_att, features, p_eatt, p_agg);

    // 3. pre = agg * softmax_e(eatt)
    softmax_mul<<<dim3(DD / 32, BB), dim3(32, 8)>>>(p_eatt, p_agg, p_pre);

    // 4. ef = pre @ vc_Wp^T  -> edge output (also input to step 5)
    gemm_xwt<<<(BB * EE) / 128, 256>>>(p_pre, vc_Wp, out_edge);

    // 5. w = inc @ ef                    [B, M, D]
    gemm_incE<<<dim3(MM / 128, 1, BB), 256>>>(inc, out_edge, p_w);

    // 6. node = w @ ec_Wp^T -> node output
    gemm_xwt<<<(BB * MM) / 128, 256>>>(p_w, ec_Wp, out_node);
}

// round 3
// speedup vs baseline: 2.7420x; 2.7420x over previous
#include <cuda_runtime.h>
#include <cuda_bf16.h>
#include <math.h>
#include <stdint.h>

// Problem constants (fixed by setup_inputs)
#define BB 8
#define MM 4096
#define EE 2048
#define DD 128

#define NODE_ELEMS (BB*MM*DD)   // 4,194,304
#define EDGE_ELEMS (BB*EE*DD)   // 2,097,152

// ---------------------------------------------------------------------------
// Scratch (device globals; no allocation allowed)
// ---------------------------------------------------------------------------
__device__ float g_att [NODE_ELEMS];               // feat @ Wa^T
__device__ float g_eatt[EDGE_ELEMS];               // inc^T @ att
__device__ float g_agg [EDGE_ELEMS];               // inc^T @ feat
__device__ float g_pre [EDGE_ELEMS];               // agg * softmax_e(eatt)
__device__ float g_w   [NODE_ELEMS];               // inc @ ef
__device__ __nv_bfloat16 g_inc_bf [(size_t)BB*MM*EE];   // inc bf16   [B,M,E]
__device__ __nv_bfloat16 g_incT_bf[(size_t)BB*EE*MM];   // inc^T bf16 [B,E,M]
__device__ __nv_bfloat16 g_attT_hi [(size_t)BB*DD*MM];  // [B,128,M]
__device__ __nv_bfloat16 g_attT_lo [(size_t)BB*DD*MM];
__device__ __nv_bfloat16 g_featT_hi[(size_t)BB*DD*MM];
__device__ __nv_bfloat16 g_featT_lo[(size_t)BB*DD*MM];
__device__ __nv_bfloat16 g_efT_hi  [(size_t)BB*DD*EE];  // [B,128,E]
__device__ __nv_bfloat16 g_efT_lo  [(size_t)BB*DD*EE];

// ---------------------------------------------------------------------------
// PTX helpers (baseline ISA only: cp.async / ldmatrix / mma.sync)
// ---------------------------------------------------------------------------
__device__ __forceinline__ uint32_t smem_u32(const void* p) {
    uint32_t a;
    asm("{ .reg .u64 t; cvta.to.shared.u64 t, %1; cvt.u32.u64 %0, t; }"
        : "=r"(a) : "l"(p));
    return a;
}
__device__ __forceinline__ void cp16(uint32_t s, const void* g) {
    asm volatile("cp.async.cg.shared.global [%0], [%1], 16;" :: "r"(s), "l"(g));
}
__device__ __forceinline__ void cp_commit() {
    asm volatile("cp.async.commit_group;" ::: "memory");
}
template<int N>
__device__ __forceinline__ void cp_wait() {
    asm volatile("cp.async.wait_group %0;" :: "n"(N) : "memory");
}
__device__ __forceinline__ void ldsm4(uint32_t r[4], uint32_t a) {
    asm volatile("ldmatrix.sync.aligned.m8n8.x4.shared.b16 {%0,%1,%2,%3}, [%4];"
                 : "=r"(r[0]), "=r"(r[1]), "=r"(r[2]), "=r"(r[3]) : "r"(a));
}
__device__ __forceinline__ void hmma(float c[4], const uint32_t a[4],
                                     uint32_t b0, uint32_t b1) {
    asm volatile("mma.sync.aligned.m16n8k16.row.col.f32.bf16.bf16.f32 "
                 "{%0,%1,%2,%3}, {%4,%5,%6,%7}, {%8,%9}, {%0,%1,%2,%3};"
                 : "+f"(c[0]), "+f"(c[1]), "+f"(c[2]), "+f"(c[3])
                 : "r"(a[0]), "r"(a[1]), "r"(a[2]), "r"(a[3]), "r"(b0), "r"(b1));
}

#define SWZ(x) ((x) ^ (((x) >> 3) & 0x70))

// ---------------------------------------------------------------------------
// Big HMMA GEMM:  C_o[row, d] = sum_k A[row,k] * (B_oh[d,k] + B_ol[d,k])
// A: bf16 [rows, KT] row-major per batch (k contiguous)
// B: bf16 [128, KT] per batch (k contiguous) -- hi/lo pair per output
// C: fp32 [rows, 128] per batch. NOUT outputs share the A operand.
// grid (rows/128, 1, BB), 256 threads (8 warps in 2x4 e/d grid).
// ---------------------------------------------------------------------------
template<int KT, int NOUT>
__global__ __launch_bounds__(256)
void mma_big(const __nv_bfloat16* __restrict__ A,
             const __nv_bfloat16* __restrict__ B0h, const __nv_bfloat16* __restrict__ B0l,
             const __nv_bfloat16* __restrict__ B1h, const __nv_bfloat16* __restrict__ B1l,
             float* __restrict__ C0, float* __restrict__ C1, int rows) {
    constexpr int S  = KT / 64;          // K stages (64 bf16 = 128B per row/stage)
    constexpr int NT = 1 + 2 * NOUT;     // tiles per stage
    constexpr int TILEB = 128 * 128;     // 16 KB per tile

    extern __shared__ __align__(1024) uint8_t smem_raw[];
    const uint32_t sb = (smem_u32(smem_raw) + 1023u) & ~1023u;

    const int tid = threadIdx.x;
    const int wid = tid >> 5, lane = tid & 31;
    const int wrow = wid >> 2;           // 0..1  (64 output rows each)
    const int wcol = wid & 3;            // 0..3  (32 d cols each)
    const int b = blockIdx.z;
    const int row0 = blockIdx.x * 128;

    const char* G[5];
    G[0] = (const char*)(A + ((size_t)b * rows + row0) * KT);
    G[1] = (const char*)(B0h + (size_t)b * 128 * KT);
    G[2] = (const char*)(B0l + (size_t)b * 128 * KT);
    if (NOUT == 2) {
        G[3] = (const char*)(B1h + (size_t)b * 128 * KT);
        G[4] = (const char*)(B1l + (size_t)b * 128 * KT);
    }

    // stage loader: copies NT tiles of [128 rows x 128 bytes] with swizzle
    auto load_stage = [&](int s) {
        const uint32_t tb = sb + (uint32_t)(s & 1) * NT * TILEB;
        const size_t gk = (size_t)s * 128;   // byte offset of k0 within a row
#pragma unroll
        for (int t = 0; t < NT; t++) {
            const char* gt = G[t] + gk;
            const uint32_t st = tb + t * TILEB;
#pragma unroll
            for (int i = 0; i < 4; i++) {
                int c = tid + i * 256;       // 0..1023
                int r = c >> 3, ch = c & 7;
                cp16(st + SWZ(r * 128 + ch * 16),
                     gt + (size_t)r * (KT * 2) + ch * 16);
            }
        }
        cp_commit();
    };

    float acc[NOUT][4][4][4];
#pragma unroll
    for (int o = 0; o < NOUT; o++)
#pragma unroll
        for (int mi = 0; mi < 4; mi++)
#pragma unroll
            for (int nj = 0; nj < 4; nj++)
#pragma unroll
                for (int q = 0; q < 4; q++) acc[o][mi][nj][q] = 0.0f;

    load_stage(0);

    const int lr = lane & 15;            // ldmatrix row within 16
    const int lc = (lane >> 4) * 16;     // ldmatrix byte col (0 or 16)

    for (int s = 0; s < S; s++) {
        if (s + 1 < S) { load_stage(s + 1); cp_wait<1>(); }
        else          { cp_wait<0>(); }
        __syncthreads();

        const uint32_t tb = sb + (uint32_t)(s & 1) * NT * TILEB;
        const uint32_t At = tb;

#pragma unroll
        for (int ks = 0; ks < 4; ks++) {
            const int kb = ks * 32;      // byte offset of this k16 within tile row
            uint32_t a[4][4];
#pragma unroll
            for (int mi = 0; mi < 4; mi++) {
                uint32_t addr = At + SWZ((wrow * 64 + mi * 16 + lr) * 128 + kb + lc);
                ldsm4(a[mi], addr);
            }
#pragma unroll
            for (int o = 0; o < NOUT; o++) {
#pragma unroll
                for (int h = 0; h < 2; h++) {
                    const uint32_t Bt = tb + (1 + o * 2 + h) * TILEB;
                    uint32_t bb[2][4];
#pragma unroll
                    for (int n2 = 0; n2 < 2; n2++) {
                        uint32_t addr = Bt + SWZ((wcol * 32 + n2 * 16 + lr) * 128 + kb + lc);
                        ldsm4(bb[n2], addr);
                    }
#pragma unroll
                    for (int mi = 0; mi < 4; mi++)
#pragma unroll
                        for (int nj = 0; nj < 4; nj++) {
                            uint32_t b0 = bb[nj >> 1][nj & 1];
                            uint32_t b1 = bb[nj >> 1][2 + (nj & 1)];
                            hmma(acc[o][mi][nj], a[mi], b0, b1);
                        }
                }
            }
        }
        __syncthreads();
    }

    // epilogue: direct fp32 stores
    const int gr = lane >> 2, tc = lane & 3;
#pragma unroll
    for (int o = 0; o < NOUT; o++) {
        float* C = (o ? C1 : C0) +
                   ((size_t)b * rows + row0 + wrow * 64) * 128 + wcol * 32;
#pragma unroll
        for (int mi = 0; mi < 4; mi++)
#pragma unroll
            for (int nj = 0; nj < 4; nj++) {
                float* p0 = C + (mi * 16 + gr) * 128 + nj * 8 + tc * 2;
                float* p1 = p0 + 8 * 128;
                *(float2*)p0 = make_float2(acc[o][mi][nj][0], acc[o][mi][nj][1]);
                *(float2*)p1 = make_float2(acc[o][mi][nj][2], acc[o][mi][nj][3]);
            }
    }
}

// ---------------------------------------------------------------------------
// inc fp32 [B,M,E] -> bf16 [B,M,E] and transposed bf16 [B,E,M]
// grid (E/64, M/64, B), 256 threads, 64x64 tiles
// ---------------------------------------------------------------------------
__global__ __launch_bounds__(256)
void conv_inc(const float* __restrict__ inc, __nv_bfloat16* __restrict__ incN,
              __nv_bfloat16* __restrict__ incT) {
    __shared__ float t[64][65];
    const int b = blockIdx.z;
    const int e0 = blockIdx.x * 64, m0 = blockIdx.y * 64;
    const float* src = inc + ((size_t)b * MM + m0) * EE + e0;
    const int tid = threadIdx.x;

#pragma unroll
    for (int i = 0; i < 4; i++) {
        int q = tid + i * 256;           // 0..1023 float4 groups
        int r = q >> 4, c4 = q & 15;
        float4 v = *(const float4*)(src + (size_t)r * EE + c4 * 4);
        t[r][c4 * 4 + 0] = v.x; t[r][c4 * 4 + 1] = v.y;
        t[r][c4 * 4 + 2] = v.z; t[r][c4 * 4 + 3] = v.w;
        __nv_bfloat162 p0 = {__float2bfloat16(v.x), __float2bfloat16(v.y)};
        __nv_bfloat162 p1 = {__float2bfloat16(v.z), __float2bfloat16(v.w)};
        uint2 pk = {*(uint32_t*)&p0, *(uint32_t*)&p1};
        *(uint2*)(incN + ((size_t)b * MM + m0 + r) * EE + e0 + c4 * 4) = pk;
    }
    __syncthreads();
#pragma unroll
    for (int i = 0; i < 4; i++) {
        int q = tid + i * 256;
        int r = q >> 4, m4 = q & 15;     // r = local e, m4*4 = local m
        __nv_bfloat162 p0 = {__float2bfloat16(t[m4 * 4 + 0][r]),
                             __float2bfloat16(t[m4 * 4 + 1][r])};
        __nv_bfloat162 p1 = {__float2bfloat16(t[m4 * 4 + 2][r]),
                             __float2bfloat16(t[m4 * 4 + 3][r])};
        uint2 pk = {*(uint32_t*)&p0, *(uint32_t*)&p1};
        *(uint2*)(incT + ((size_t)b * EE + e0 + r) * MM + m0 + m4 * 4) = pk;
    }
}

// ---------------------------------------------------------------------------
// X fp32 [B,R,128] -> transposed hi/lo bf16 [B,128,R]
// grid (R/64, B), 256 threads
// ---------------------------------------------------------------------------
__global__ __launch_bounds__(256)
void conv_hiloT(const float* __restrict__ X, __nv_bfloat16* __restrict__ Th,
                __nv_bfloat16* __restrict__ Tl, int R) {
    __shared__ float t[64][129];
    const int b = blockIdx.y;
    const int r0 = blockIdx.x * 64;
    const float* Xb = X + ((size_t)b * R + r0) * 128;
    const int tid = threadIdx.x;

#pragma unroll
    for (int i = 0; i < 8; i++) {
        int q = tid + i * 256;           // 0..2047 float4 groups
        int r = q >> 5, c4 = q & 31;
        float4 v = *(const float4*)(Xb + (size_t)r * 128 + c4 * 4);
        t[r][c4 * 4 + 0] = v.x; t[r][c4 * 4 + 1] = v.y;
        t[r][c4 * 4 + 2] = v.z; t[r][c4 * 4 + 3] = v.w;
    }
    __syncthreads();
#pragma unroll
    for (int i = 0; i < 8; i++) {
        int q = tid + i * 256;
        int d = q >> 4, m4 = q & 15;     // d = out row, m4*4 = local col
        __nv_bfloat16 hi[4], lo[4];
#pragma unroll
        for (int j = 0; j < 4; j++) {
            float v = t[m4 * 4 + j][d];
            hi[j] = __float2bfloat16(v);
            lo[j] = __float2bfloat16(v - __bfloat162float(hi[j]));
        }
        size_t off = ((size_t)b * 128 + d) * R + r0 + m4 * 4;
        __nv_bfloat162 h0 = {hi[0], hi[1]}, h1 = {hi[2], hi[3]};
        __nv_bfloat162 l0 = {lo[0], lo[1]}, l1 = {lo[2], lo[3]};
        uint2 ph = {*(uint32_t*)&h0, *(uint32_t*)&h1};
        uint2 pl = {*(uint32_t*)&l0, *(uint32_t*)&l1};
        *(uint2*)(Th + off) = ph;
        *(uint2*)(Tl + off) = pl;
    }
}

// ---------------------------------------------------------------------------
// Small FFMA GEMM: C[r, j] = sum_k X[r,k] * W[j,k]  (d x d weights)
// ---------------------------------------------------------------------------
__device__ __forceinline__ void mma_tile_f(const float (*As)[128], const float (*Bs)[128],
                                           float acc[8][8], int tx, int ty) {
#pragma unroll
    for (int k = 0; k < 16; k++) {
        float a[8], bv[8];
        *(float4*)(a)      = *(const float4*)&As[k][ty * 8];
        *(float4*)(a + 4)  = *(const float4*)&As[k][ty * 8 + 4];
        *(float4*)(bv)     = *(const float4*)&Bs[k][tx * 8];
        *(float4*)(bv + 4) = *(const float4*)&Bs[k][tx * 8 + 4];
#pragma unroll
        for (int i = 0; i < 8; i++)
#pragma unroll
            for (int j = 0; j < 8; j++)
                acc[i][j] = fmaf(a[i], bv[j], acc[i][j]);
    }
}

__global__ __launch_bounds__(256)
void gemm_xwt(const float* __restrict__ X, const float* __restrict__ W,
              float* __restrict__ C) {
    __shared__ float As[16][128];
    __shared__ float Bs[16][128];
    const int tid = threadIdx.x;
    const int tx = tid & 15, ty = tid >> 4;
    const size_t r0 = (size_t)blockIdx.x * 128;

    float acc[8][8];
#pragma unroll
    for (int i = 0; i < 8; i++)
#pragma unroll
        for (int j = 0; j < 8; j++) acc[i][j] = 0.0f;

    for (int k0 = 0; k0 < 128; k0 += 16) {
#pragma unroll
        for (int l = 0; l < 2; l++) {
            int q = tid * 2 + l;
            int row = q >> 2, kq = q & 3;
            float4 va = *(const float4*)(X + (r0 + row) * 128 + k0 + kq * 4);
            As[kq * 4 + 0][row] = va.x; As[kq * 4 + 1][row] = va.y;
            As[kq * 4 + 2][row] = va.z; As[kq * 4 + 3][row] = va.w;
            float4 vb = *(const float4*)(W + (size_t)row * 128 + k0 + kq * 4);
            Bs[kq * 4 + 0][row] = vb.x; Bs[kq * 4 + 1][row] = vb.y;
            Bs[kq * 4 + 2][row] = vb.z; Bs[kq * 4 + 3][row] = vb.w;
        }
        __syncthreads();
        mma_tile_f(As, Bs, acc, tx, ty);
        __syncthreads();
    }
#pragma unroll
    for (int i = 0; i < 8; i++) {
        float* crow = C + (r0 + (size_t)(ty * 8 + i)) * 128 + tx * 8;
        *(float4*)crow       = make_float4(acc[i][0], acc[i][1], acc[i][2], acc[i][3]);
        *(float4*)(crow + 4) = make_float4(acc[i][4], acc[i][5], acc[i][6], acc[i][7]);
    }
}

// ---------------------------------------------------------------------------
// pre[b,e,d] = agg[b,e,d] * softmax over e of eatt[b,:,d]
// ---------------------------------------------------------------------------
__global__ __launch_bounds__(256)
void softmax_mul(const float* __restrict__ eatt, const float* __restrict__ agg,
                 float* __restrict__ pre) {
    const int b = blockIdx.y;
    const int d = blockIdx.x * 32 + threadIdx.x;
    const int ey = threadIdx.y;
    const float* Eb = eatt + (size_t)b * EE * DD;
    const float* Ab = agg  + (size_t)b * EE * DD;
    float* Pb = pre + (size_t)b * EE * DD;

    __shared__ float rmax[8][32];
    __shared__ float rsum[8][32];

    float mx = -3.0e38f;
    for (int e = ey; e < EE; e += 8)
        mx = fmaxf(mx, Eb[(size_t)e * DD + d]);
    rmax[ey][threadIdx.x] = mx;
    __syncthreads();
    float m = rmax[0][threadIdx.x];
#pragma unroll
    for (int i = 1; i < 8; i++) m = fmaxf(m, rmax[i][threadIdx.x]);

    float s = 0.0f;
    for (int e = ey; e < EE; e += 8)
        s += expf(Eb[(size_t)e * DD + d] - m);
    rsum[ey][threadIdx.x] = s;
    __syncthreads();
    float sum = 0.0f;
#pragma unroll
    for (int i = 0; i < 8; i++) sum += rsum[i][threadIdx.x];
    const float inv = 1.0f / sum;

    for (int e = ey; e < EE; e += 8) {
        size_t idx = (size_t)e * DD + d;
        Pb[idx] = Ab[idx] * expf(Eb[idx] - m) * inv;
    }
}

// ---------------------------------------------------------------------------
// Launch. The n_layers recurrence is a fixed point (ef_{k+1} = a*ef_k +
// (1-a)*ef_base with ef_1 = ef_base), so one pass suffices; ec_Wa is dead.
// Precision: inc is {0,1} -> exact in bf16; fp32 operands use hi/lo bf16
// split (residual <= 2^-16 relative); HMMA accumulates in fp32.
// ---------------------------------------------------------------------------
extern "C" void kernel_launch(void* const* d_in, const int* in_sizes, int n_in,
                              void* d_out, int out_size) {
    const float* features = (const float*)d_in[0];
    const float* inc      = (const float*)d_in[1];
    const float* vc_Wa    = (const float*)d_in[2];
    const float* vc_Wp    = (const float*)d_in[3];
    const float* ec_Wp    = (const float*)d_in[6];

    float* out_node = (float*)d_out;                 // [B,M,D]
    float* out_edge = out_node + NODE_ELEMS;         // [B,E,D]

    float *p_att, *p_eatt, *p_agg, *p_pre, *p_w;
    __nv_bfloat16 *p_incN, *p_incT, *p_attTh, *p_attTl, *p_featTh, *p_featTl, *p_efTh, *p_efTl;
    cudaGetSymbolAddress((void**)&p_att,    g_att);
    cudaGetSymbolAddress((void**)&p_eatt,   g_eatt);
    cudaGetSymbolAddress((void**)&p_agg,    g_agg);
    cudaGetSymbolAddress((void**)&p_pre,    g_pre);
    cudaGetSymbolAddress((void**)&p_w,      g_w);
    cudaGetSymbolAddress((void**)&p_incN,   g_inc_bf);
    cudaGetSymbolAddress((void**)&p_incT,   g_incT_bf);
    cudaGetSymbolAddress((void**)&p_attTh,  g_attT_hi);
    cudaGetSymbolAddress((void**)&p_attTl,  g_attT_lo);
    cudaGetSymbolAddress((void**)&p_featTh, g_featT_hi);
    cudaGetSymbolAddress((void**)&p_featTl, g_featT_lo);
    cudaGetSymbolAddress((void**)&p_efTh,   g_efT_hi);
    cudaGetSymbolAddress((void**)&p_efTl,   g_efT_lo);

    // Dynamic smem: double-buffered stages of (1 + 2*NOUT) x 16KB tiles
    const int SMEM2 = 2 * 5 * 16384 + 1024;   // 164864 (NOUT=2)
    const int SMEM1 = 2 * 3 * 16384 + 1024;   //  99328 (NOUT=1)
    cudaFuncSetAttribute(mma_big<MM, 2>, cudaFuncAttributeMaxDynamicSharedMemorySize, SMEM2);
    cudaFuncSetAttribute(mma_big<EE, 1>, cudaFuncAttributeMaxDynamicSharedMemorySize, SMEM1);

    // 1. att = feat @ vc_Wa^T
    gemm_xwt<<<(BB * MM) / 128, 256>>>(features, vc_Wa, p_att);

    // 2. inc -> bf16 (both layouts)
    conv_inc<<<dim3(EE / 64, MM / 64, BB), 256>>>(inc, p_incN, p_incT);

    // 3. att, feat -> transposed hi/lo bf16 [B,128,M]
    conv_hiloT<<<dim3(MM / 64, BB), 256>>>(p_att, p_attTh, p_attTl, MM);
    conv_hiloT<<<dim3(MM / 64, BB), 256>>>(features, p_featTh, p_featTl, MM);

    // 4. eatt = inc^T @ att ; agg = inc^T @ feat   (HMMA, shared A)
    mma_big<MM, 2><<<dim3(EE / 128, 1, BB), 256, SMEM2>>>(
        p_incT, p_attTh, p_attTl, p_featTh, p_featTl, p_eatt, p_agg, EE);

    // 5. pre = agg * softmax_e(eatt)
    softmax_mul<<<dim3(DD / 32, BB), dim3(32, 8)>>>(p_eatt, p_agg, p_pre);

    // 6. ef = pre @ vc_Wp^T -> edge output
    gemm_xwt<<<(BB * EE) / 128, 256>>>(p_pre, vc_Wp, out_edge);

    // 7. ef -> transposed hi/lo bf16 [B,128,E]
    conv_hiloT<<<dim3(EE / 64, BB), 256>>>(out_edge, p_efTh, p_efTl, EE);

    // 8. w = inc @ ef   (HMMA)
    mma_big<EE, 1><<<dim3(MM / 128, 1, BB), 256, SMEM1>>>(
        p_incN, p_efTh, p_efTl, nullptr, nullptr, p_w, nullptr, MM);

    // 9. node = w @ ec_Wp^T -> node output
    gemm_xwt<<<(BB * MM) / 128, 256>>>(p_w, ec_Wp, out_node);
}

// round 4
// speedup vs baseline: 3.3858x; 1.2348x over previous
#include <cuda_runtime.h>
#include <cuda_bf16.h>
#include <math.h>
#include <stdint.h>

// Problem constants (fixed by setup_inputs)
#define BB 8
#define MM 4096
#define EE 2048
#define DD 128

#define NODE_ELEMS (BB*MM*DD)   // 4,194,304
#define EDGE_ELEMS (BB*EE*DD)   // 2,097,152

// ---------------------------------------------------------------------------
// Scratch (device globals; no allocation allowed)
// ---------------------------------------------------------------------------
__device__ float g_eatt[EDGE_ELEMS];               // agg @ Wa^T
__device__ float g_agg [EDGE_ELEMS];               // inc^T @ feat
__device__ float g_pre [EDGE_ELEMS];               // agg * softmax_e(eatt)
__device__ float g_w   [NODE_ELEMS];               // inc @ ef
__device__ __nv_bfloat16 g_inc_bf [(size_t)BB*MM*EE];   // inc bf16   [B,M,E]
__device__ __nv_bfloat16 g_incT_bf[(size_t)BB*EE*MM];   // inc^T bf16 [B,E,M]
__device__ __nv_bfloat16 g_featT_hi[(size_t)BB*DD*MM];  // [B,128,M]
__device__ __nv_bfloat16 g_featT_lo[(size_t)BB*DD*MM];
__device__ __nv_bfloat16 g_efT_hi  [(size_t)BB*DD*EE];  // [B,128,E]
__device__ __nv_bfloat16 g_efT_lo  [(size_t)BB*DD*EE];

// ---------------------------------------------------------------------------
// PTX helpers (baseline ISA only: cp.async / ldmatrix / mma.sync)
// ---------------------------------------------------------------------------
__device__ __forceinline__ uint32_t smem_u32(const void* p) {
    uint32_t a;
    asm("{ .reg .u64 t; cvta.to.shared.u64 t, %1; cvt.u32.u64 %0, t; }"
        : "=r"(a) : "l"(p));
    return a;
}
__device__ __forceinline__ void cp16(uint32_t s, const void* g) {
    asm volatile("cp.async.cg.shared.global [%0], [%1], 16;" :: "r"(s), "l"(g));
}
__device__ __forceinline__ void cp_commit() {
    asm volatile("cp.async.commit_group;" ::: "memory");
}
template<int N>
__device__ __forceinline__ void cp_wait() {
    asm volatile("cp.async.wait_group %0;" :: "n"(N) : "memory");
}
__device__ __forceinline__ void ldsm4(uint32_t r[4], uint32_t a) {
    asm volatile("ldmatrix.sync.aligned.m8n8.x4.shared.b16 {%0,%1,%2,%3}, [%4];"
                 : "=r"(r[0]), "=r"(r[1]), "=r"(r[2]), "=r"(r[3]) : "r"(a));
}
__device__ __forceinline__ void hmma(float c[4], const uint32_t a[4],
                                     uint32_t b0, uint32_t b1) {
    asm volatile("mma.sync.aligned.m16n8k16.row.col.f32.bf16.bf16.f32 "
                 "{%0,%1,%2,%3}, {%4,%5,%6,%7}, {%8,%9}, {%0,%1,%2,%3};"
                 : "+f"(c[0]), "+f"(c[1]), "+f"(c[2]), "+f"(c[3])
                 : "r"(a[0]), "r"(a[1]), "r"(a[2]), "r"(a[3]), "r"(b0), "r"(b1));
}

#define SWZ(x) ((x) ^ (((x) >> 3) & 0x70))

// ---------------------------------------------------------------------------
// Big HMMA GEMM:  C[row, d] = sum_k A[row,k] * (Bh[d,k] + Bl[d,k])
// A: bf16 [rows, KT] row-major per batch (k contiguous)
// B: bf16 [128, KT] per batch (k contiguous) -- hi/lo pair
// C: fp32 [rows, 128] per batch.
// grid (rows/128, 1, BB), 256 threads (8 warps in 2x4 grid), 3-stage pipeline.
// ---------------------------------------------------------------------------
template<int KT>
__global__ __launch_bounds__(256)
void mma_big(const __nv_bfloat16* __restrict__ A,
             const __nv_bfloat16* __restrict__ Bh, const __nv_bfloat16* __restrict__ Bl,
             float* __restrict__ C, int rows) {
    constexpr int S  = KT / 64;          // K stages (64 bf16 = 128B per row/stage)
    constexpr int NT = 3;                // tiles per stage (A, Bh, Bl)
    constexpr int TILEB = 128 * 128;     // 16 KB per tile
    constexpr int NBUF = 3;              // pipeline depth

    extern __shared__ __align__(1024) uint8_t smem_raw[];
    const uint32_t sb = (smem_u32(smem_raw) + 1023u) & ~1023u;

    const int tid = threadIdx.x;
    const int wid = tid >> 5, lane = tid & 31;
    const int wrow = wid >> 2;           // 0..1  (64 output rows each)
    const int wcol = wid & 3;            // 0..3  (32 d cols each)
    const int b = blockIdx.z;
    const int row0 = blockIdx.x * 128;

    const char* G[3];
    G[0] = (const char*)(A + ((size_t)b * rows + row0) * KT);
    G[1] = (const char*)(Bh + (size_t)b * 128 * KT);
    G[2] = (const char*)(Bl + (size_t)b * 128 * KT);

    auto load_stage = [&](int s) {
        const uint32_t tb = sb + (uint32_t)(s % NBUF) * NT * TILEB;
        const size_t gk = (size_t)s * 128;     // byte offset of k0 within a row
#pragma unroll
        for (int t = 0; t < NT; t++) {
            const char* gt = G[t] + gk;
            const uint32_t st = tb + t * TILEB;
#pragma unroll
            for (int i = 0; i < 4; i++) {
                int c = tid + i * 256;          // 0..1023
                int r = c >> 3, ch = c & 7;
                cp16(st + SWZ(r * 128 + ch * 16),
                     gt + (size_t)r * (KT * 2) + ch * 16);
            }
        }
        cp_commit();
    };

    float acc[4][4][4];
#pragma unroll
    for (int mi = 0; mi < 4; mi++)
#pragma unroll
        for (int nj = 0; nj < 4; nj++)
#pragma unroll
            for (int q = 0; q < 4; q++) acc[mi][nj][q] = 0.0f;

    load_stage(0);
    load_stage(1);

    const int lr = lane & 15;            // ldmatrix row within 16
    const int lc = (lane >> 4) * 16;     // ldmatrix byte col (0 or 16)

    for (int s = 0; s < S; s++) {
        if (s + 2 < S)      { load_stage(s + 2); cp_wait<2>(); }
        else if (s + 1 < S) { cp_wait<1>(); }
        else                { cp_wait<0>(); }
        __syncthreads();

        const uint32_t tb = sb + (uint32_t)(s % NBUF) * NT * TILEB;

#pragma unroll
        for (int ks = 0; ks < 4; ks++) {
            const int kb = ks * 32;      // byte offset of this k16 within tile row
            uint32_t a[4][4];
#pragma unroll
            for (int mi = 0; mi < 4; mi++) {
                uint32_t addr = tb + SWZ((wrow * 64 + mi * 16 + lr) * 128 + kb + lc);
                ldsm4(a[mi], addr);
            }
#pragma unroll
            for (int h = 0; h < 2; h++) {
                const uint32_t Bt = tb + (1 + h) * TILEB;
                uint32_t bb[2][4];
#pragma unroll
                for (int n2 = 0; n2 < 2; n2++) {
                    uint32_t addr = Bt + SWZ((wcol * 32 + n2 * 16 + lr) * 128 + kb + lc);
                    ldsm4(bb[n2], addr);
                }
#pragma unroll
                for (int mi = 0; mi < 4; mi++)
#pragma unroll
                    for (int nj = 0; nj < 4; nj++) {
                        uint32_t b0 = bb[nj >> 1][nj & 1];
                        uint32_t b1 = bb[nj >> 1][2 + (nj & 1)];
                        hmma(acc[mi][nj], a[mi], b0, b1);
                    }
            }
        }
        __syncthreads();
    }

    // epilogue: direct fp32 stores
    const int gr = lane >> 2, tc = lane & 3;
    float* Cw = C + ((size_t)b * rows + row0 + wrow * 64) * 128 + wcol * 32;
#pragma unroll
    for (int mi = 0; mi < 4; mi++)
#pragma unroll
        for (int nj = 0; nj < 4; nj++) {
            float* p0 = Cw + (mi * 16 + gr) * 128 + nj * 8 + tc * 2;
            float* p1 = p0 + 8 * 128;
            *(float2*)p0 = make_float2(acc[mi][nj][0], acc[mi][nj][1]);
            *(float2*)p1 = make_float2(acc[mi][nj][2], acc[mi][nj][3]);
        }
}

// ---------------------------------------------------------------------------
// inc fp32 [B,M,E] -> bf16 [B,M,E] and transposed bf16 [B,E,M]
// grid (E/64, M/64, B), 256 threads, 64x64 tiles
// ---------------------------------------------------------------------------
__global__ __launch_bounds__(256)
void conv_inc(const float* __restrict__ inc, __nv_bfloat16* __restrict__ incN,
              __nv_bfloat16* __restrict__ incT) {
    __shared__ float t[64][65];
    const int b = blockIdx.z;
    const int e0 = blockIdx.x * 64, m0 = blockIdx.y * 64;
    const float* src = inc + ((size_t)b * MM + m0) * EE + e0;
    const int tid = threadIdx.x;

#pragma unroll
    for (int i = 0; i < 4; i++) {
        int q = tid + i * 256;           // 0..1023 float4 groups
        int r = q >> 4, c4 = q & 15;
        float4 v = *(const float4*)(src + (size_t)r * EE + c4 * 4);
        t[r][c4 * 4 + 0] = v.x; t[r][c4 * 4 + 1] = v.y;
        t[r][c4 * 4 + 2] = v.z; t[r][c4 * 4 + 3] = v.w;
        __nv_bfloat162 p0 = {__float2bfloat16(v.x), __float2bfloat16(v.y)};
        __nv_bfloat162 p1 = {__float2bfloat16(v.z), __float2bfloat16(v.w)};
        uint2 pk = {*(uint32_t*)&p0, *(uint32_t*)&p1};
        *(uint2*)(incN + ((size_t)b * MM + m0 + r) * EE + e0 + c4 * 4) = pk;
    }
    __syncthreads();
#pragma unroll
    for (int i = 0; i < 4; i++) {
        int q = tid + i * 256;
        int r = q >> 4, m4 = q & 15;     // r = local e, m4*4 = local m
        __nv_bfloat162 p0 = {__float2bfloat16(t[m4 * 4 + 0][r]),
                             __float2bfloat16(t[m4 * 4 + 1][r])};
        __nv_bfloat162 p1 = {__float2bfloat16(t[m4 * 4 + 2][r]),
                             __float2bfloat16(t[m4 * 4 + 3][r])};
        uint2 pk = {*(uint32_t*)&p0, *(uint32_t*)&p1};
        *(uint2*)(incT + ((size_t)b * EE + e0 + r) * MM + m0 + m4 * 4) = pk;
    }
}

// ---------------------------------------------------------------------------
// X fp32 [B,R,128] -> transposed hi/lo bf16 [B,128,R]
// grid (R/64, B), 256 threads
// ---------------------------------------------------------------------------
__global__ __launch_bounds__(256)
void conv_hiloT(const float* __restrict__ X, __nv_bfloat16* __restrict__ Th,
                __nv_bfloat16* __restrict__ Tl, int R) {
    __shared__ float t[64][129];
    const int b = blockIdx.y;
    const int r0 = blockIdx.x * 64;
    const float* Xb = X + ((size_t)b * R + r0) * 128;
    const int tid = threadIdx.x;

#pragma unroll
    for (int i = 0; i < 8; i++) {
        int q = tid + i * 256;           // 0..2047 float4 groups
        int r = q >> 5, c4 = q & 31;
        float4 v = *(const float4*)(Xb + (size_t)r * 128 + c4 * 4);
        t[r][c4 * 4 + 0] = v.x; t[r][c4 * 4 + 1] = v.y;
        t[r][c4 * 4 + 2] = v.z; t[r][c4 * 4 + 3] = v.w;
    }
    __syncthreads();
#pragma unroll
    for (int i = 0; i < 8; i++) {
        int q = tid + i * 256;
        int d = q >> 4, m4 = q & 15;     // d = out row, m4*4 = local col
        __nv_bfloat16 hi[4], lo[4];
#pragma unroll
        for (int j = 0; j < 4; j++) {
            float v = t[m4 * 4 + j][d];
            hi[j] = __float2bfloat16(v);
            lo[j] = __float2bfloat16(v - __bfloat162float(hi[j]));
        }
        size_t off = ((size_t)b * 128 + d) * R + r0 + m4 * 4;
        __nv_bfloat162 h0 = {hi[0], hi[1]}, h1 = {hi[2], hi[3]};
        __nv_bfloat162 l0 = {lo[0], lo[1]}, l1 = {lo[2], lo[3]};
        uint2 ph = {*(uint32_t*)&h0, *(uint32_t*)&h1};
        uint2 pl = {*(uint32_t*)&l0, *(uint32_t*)&l1};
        *(uint2*)(Th + off) = ph;
        *(uint2*)(Tl + off) = pl;
    }
}

// ---------------------------------------------------------------------------
// FFMA GEMM core: C[r, j] = sum_k X[r,k] * W[j,k]  (128x128 weights)
// Optionally fused transposed hi/lo bf16 output [B,128,Rb] (Rb rows/batch).
// ---------------------------------------------------------------------------
__device__ __forceinline__ void mma_tile_f(const float (*As)[128], const float (*Bs)[128],
                                           float acc[8][8], int tx, int ty) {
#pragma unroll
    for (int k = 0; k < 16; k++) {
        float a[8], bv[8];
        *(float4*)(a)      = *(const float4*)&As[k][ty * 8];
        *(float4*)(a + 4)  = *(const float4*)&As[k][ty * 8 + 4];
        *(float4*)(bv)     = *(const float4*)&Bs[k][tx * 8];
        *(float4*)(bv + 4) = *(const float4*)&Bs[k][tx * 8 + 4];
#pragma unroll
        for (int i = 0; i < 8; i++)
#pragma unroll
            for (int j = 0; j < 8; j++)
                acc[i][j] = fmaf(a[i], bv[j], acc[i][j]);
    }
}

template<bool FUSE_T>
__global__ __launch_bounds__(256)
void gemm_xwt(const float* __restrict__ X, const float* __restrict__ W,
              float* __restrict__ C, __nv_bfloat16* __restrict__ Th,
              __nv_bfloat16* __restrict__ Tl, int Rb) {
    __shared__ float As[16][128];
    __shared__ float Bs[16][128];
    const int tid = threadIdx.x;
    const int tx = tid & 15, ty = tid >> 4;
    const size_t r0 = (size_t)blockIdx.x * 128;

    float acc[8][8];
#pragma unroll
    for (int i = 0; i < 8; i++)
#pragma unroll
        for (int j = 0; j < 8; j++) acc[i][j] = 0.0f;

    for (int k0 = 0; k0 < 128; k0 += 16) {
#pragma unroll
        for (int l = 0; l < 2; l++) {
            int q = tid * 2 + l;
            int row = q >> 2, kq = q & 3;
            float4 va = *(const float4*)(X + (r0 + row) * 128 + k0 + kq * 4);
            As[kq * 4 + 0][row] = va.x; As[kq * 4 + 1][row] = va.y;
            As[kq * 4 + 2][row] = va.z; As[kq * 4 + 3][row] = va.w;
            float4 vb = *(const float4*)(W + (size_t)row * 128 + k0 + kq * 4);
            Bs[kq * 4 + 0][row] = vb.x; Bs[kq * 4 + 1][row] = vb.y;
            Bs[kq * 4 + 2][row] = vb.z; Bs[kq * 4 + 3][row] = vb.w;
        }
        __syncthreads();
        mma_tile_f(As, Bs, acc, tx, ty);
        __syncthreads();
    }
#pragma unroll
    for (int i = 0; i < 8; i++) {
        float* crow = C + (r0 + (size_t)(ty * 8 + i)) * 128 + tx * 8;
        *(float4*)crow       = make_float4(acc[i][0], acc[i][1], acc[i][2], acc[i][3]);
        *(float4*)(crow + 4) = make_float4(acc[i][4], acc[i][5], acc[i][6], acc[i][7]);
    }
    if (FUSE_T) {
        // transposed hi/lo bf16: Th/Tl[b][d][e], 8 contiguous e per thread-col
        const int b  = (int)(r0 / Rb);
        const int e0 = (int)(r0 % Rb) + ty * 8;
#pragma unroll
        for (int j = 0; j < 8; j++) {
            const int d = tx * 8 + j;
            __nv_bfloat16 hi[8], lo[8];
#pragma unroll
            for (int i = 0; i < 8; i++) {
                float v = acc[i][j];
                hi[i] = __float2bfloat16(v);
                lo[i] = __float2bfloat16(v - __bfloat162float(hi[i]));
            }
            size_t off = ((size_t)b * 128 + d) * Rb + e0;
            *(uint4*)(Th + off) = *(uint4*)hi;
            *(uint4*)(Tl + off) = *(uint4*)lo;
        }
    }
}

// ---------------------------------------------------------------------------
// pre[b,e,d] = agg[b,e,d] * softmax over e of eatt[b,:,d]
// ---------------------------------------------------------------------------
__global__ __launch_bounds__(256)
void softmax_mul(const float* __restrict__ eatt, const float* __restrict__ agg,
                 float* __restrict__ pre) {
    const int b = blockIdx.y;
    const int d = blockIdx.x * 32 + threadIdx.x;
    const int ey = threadIdx.y;
    const float* Eb = eatt + (size_t)b * EE * DD;
    const float* Ab = agg  + (size_t)b * EE * DD;
    float* Pb = pre + (size_t)b * EE * DD;

    __shared__ float rmax[8][32];
    __shared__ float rsum[8][32];

    float mx = -3.0e38f;
    for (int e = ey; e < EE; e += 8)
        mx = fmaxf(mx, Eb[(size_t)e * DD + d]);
    rmax[ey][threadIdx.x] = mx;
    __syncthreads();
    float m = rmax[0][threadIdx.x];
#pragma unroll
    for (int i = 1; i < 8; i++) m = fmaxf(m, rmax[i][threadIdx.x]);

    float s = 0.0f;
    for (int e = ey; e < EE; e += 8)
        s += expf(Eb[(size_t)e * DD + d] - m);
    rsum[ey][threadIdx.x] = s;
    __syncthreads();
    float sum = 0.0f;
#pragma unroll
    for (int i = 0; i < 8; i++) sum += rsum[i][threadIdx.x];
    const float inv = 1.0f / sum;

    for (int e = ey; e < EE; e += 8) {
        size_t idx = (size_t)e * DD + d;
        Pb[idx] = Ab[idx] * expf(Eb[idx] - m) * inv;
    }
}

// ---------------------------------------------------------------------------
// Launch.
// Identities used:
//  * n_layers recurrence is a fixed point -> one pass; ec_Wa is dead code.
//  * eatt = inc^T @ (feat @ Wa^T) = (inc^T @ feat) @ Wa^T = agg @ Wa^T,
//    so the big GEMM produces only agg; eatt is a tiny d x d GEMM.
// Precision: inc is {0,1} -> exact in bf16; fp32 operands use hi/lo bf16
// split (residual <= 2^-16 relative); HMMA accumulates in fp32.
// ---------------------------------------------------------------------------
extern "C" void kernel_launch(void* const* d_in, const int* in_sizes, int n_in,
                              void* d_out, int out_size) {
    const float* features = (const float*)d_in[0];
    const float* inc      = (const float*)d_in[1];
    const float* vc_Wa    = (const float*)d_in[2];
    const float* vc_Wp    = (const float*)d_in[3];
    const float* ec_Wp    = (const float*)d_in[6];

    float* out_node = (float*)d_out;                 // [B,M,D]
    float* out_edge = out_node + NODE_ELEMS;         // [B,E,D]

    float *p_eatt, *p_agg, *p_pre, *p_w;
    __nv_bfloat16 *p_incN, *p_incT, *p_featTh, *p_featTl, *p_efTh, *p_efTl;
    cudaGetSymbolAddress((void**)&p_eatt,   g_eatt);
    cudaGetSymbolAddress((void**)&p_agg,    g_agg);
    cudaGetSymbolAddress((void**)&p_pre,    g_pre);
    cudaGetSymbolAddress((void**)&p_w,      g_w);
    cudaGetSymbolAddress((void**)&p_incN,   g_inc_bf);
    cudaGetSymbolAddress((void**)&p_incT,   g_incT_bf);
    cudaGetSymbolAddress((void**)&p_featTh, g_featT_hi);
    cudaGetSymbolAddress((void**)&p_featTl, g_featT_lo);
    cudaGetSymbolAddress((void**)&p_efTh,   g_efT_hi);
    cudaGetSymbolAddress((void**)&p_efTl,   g_efT_lo);

    // Dynamic smem: 3-buffered stages of 3 x 16KB tiles
    const int SMEM = 3 * 3 * 16384 + 1024;   // 148480
    cudaFuncSetAttribute(mma_big<MM>, cudaFuncAttributeMaxDynamicSharedMemorySize, SMEM);
    cudaFuncSetAttribute(mma_big<EE>, cudaFuncAttributeMaxDynamicSharedMemorySize, SMEM);

    // 1. inc -> bf16 (both layouts)
    conv_inc<<<dim3(EE / 64, MM / 64, BB), 256>>>(inc, p_incN, p_incT);

    // 2. feat -> transposed hi/lo bf16 [B,128,M]
    conv_hiloT<<<dim3(MM / 64, BB), 256>>>(features, p_featTh, p_featTl, MM);

    // 3. agg = inc^T @ feat   (HMMA)
    mma_big<MM><<<dim3(EE / 128, 1, BB), 256, SMEM>>>(
        p_incT, p_featTh, p_featTl, p_agg, EE);

    // 4. eatt = agg @ vc_Wa^T   (tiny FFMA GEMM)
    gemm_xwt<false><<<(BB * EE) / 128, 256>>>(p_agg, vc_Wa, p_eatt,
                                              nullptr, nullptr, EE);

    // 5. pre = agg * softmax_e(eatt)
    softmax_mul<<<dim3(DD / 32, BB), dim3(32, 8)>>>(p_eatt, p_agg, p_pre);

    // 6. ef = pre @ vc_Wp^T -> edge output + fused efT hi/lo
    gemm_xwt<true><<<(BB * EE) / 128, 256>>>(p_pre, vc_Wp, out_edge,
                                             p_efTh, p_efTl, EE);

    // 7. w = inc @ ef   (HMMA)
    mma_big<EE><<<dim3(MM / 128, 1, BB), 256, SMEM>>>(
        p_incN, p_efTh, p_efTl, p_w, MM);

    // 8. node = w @ ec_Wp^T -> node output
    gemm_xwt<false><<<(BB * MM) / 128, 256>>>(p_w, ec_Wp, out_node,
                                              nullptr, nullptr, MM);
}

// round 5
// speedup vs baseline: 3.8859x; 1.1477x over previous
#include <cuda_runtime.h>
#include <cuda_bf16.h>
#include <math.h>
#include <stdint.h>

// Problem constants (fixed by setup_inputs)
#define BB 8
#define MM 4096
#define EE 2048
#define DD 128

#define NODE_ELEMS (BB*MM*DD)   // 4,194,304
#define EDGE_ELEMS (BB*EE*DD)   // 2,097,152

// ---------------------------------------------------------------------------
// Scratch (device globals; no allocation allowed)
// ---------------------------------------------------------------------------
__device__ float g_eatt[EDGE_ELEMS];               // agg @ Wa^T (fused epi)
__device__ float g_agg [EDGE_ELEMS];               // inc^T @ feat
__device__ float g_pre [EDGE_ELEMS];               // agg * softmax_e(eatt)
__device__ __nv_bfloat16 g_inc_bf [(size_t)BB*MM*EE];   // inc bf16 [B,M,E]
__device__ __nv_bfloat16 g_featT_hi[(size_t)BB*DD*MM];  // [B,128,M]
__device__ __nv_bfloat16 g_featT_lo[(size_t)BB*DD*MM];
__device__ __nv_bfloat16 g_efT_hi  [(size_t)BB*DD*EE];  // [B,128,E]
__device__ __nv_bfloat16 g_efT_lo  [(size_t)BB*DD*EE];
__device__ __nv_bfloat16 g_WaH[DD*DD], g_WaL[DD*DD];    // vc_Wa hi/lo
__device__ __nv_bfloat16 g_WpH[DD*DD], g_WpL[DD*DD];    // ec_Wp hi/lo

// ---------------------------------------------------------------------------
// PTX helpers (baseline ISA only: cp.async / ldmatrix / mma.sync)
// ---------------------------------------------------------------------------
__device__ __forceinline__ uint32_t smem_u32(const void* p) {
    uint32_t a;
    asm("{ .reg .u64 t; cvta.to.shared.u64 t, %1; cvt.u32.u64 %0, t; }"
        : "=r"(a) : "l"(p));
    return a;
}
__device__ __forceinline__ void cp16(uint32_t s, const void* g) {
    asm volatile("cp.async.cg.shared.global [%0], [%1], 16;" :: "r"(s), "l"(g));
}
__device__ __forceinline__ void cp_commit() {
    asm volatile("cp.async.commit_group;" ::: "memory");
}
template<int N>
__device__ __forceinline__ void cp_wait() {
    asm volatile("cp.async.wait_group %0;" :: "n"(N) : "memory");
}
__device__ __forceinline__ void ldsm4(uint32_t r[4], uint32_t a) {
    asm volatile("ldmatrix.sync.aligned.m8n8.x4.shared.b16 {%0,%1,%2,%3}, [%4];"
                 : "=r"(r[0]), "=r"(r[1]), "=r"(r[2]), "=r"(r[3]) : "r"(a));
}
__device__ __forceinline__ void ldsm4t(uint32_t r[4], uint32_t a) {
    asm volatile("ldmatrix.sync.aligned.m8n8.x4.trans.shared.b16 {%0,%1,%2,%3}, [%4];"
                 : "=r"(r[0]), "=r"(r[1]), "=r"(r[2]), "=r"(r[3]) : "r"(a));
}
__device__ __forceinline__ void sts32(uint32_t a, uint32_t v) {
    asm volatile("st.shared.b32 [%0], %1;" :: "r"(a), "r"(v) : "memory");
}
__device__ __forceinline__ void hmma(float c[4], const uint32_t a[4],
                                     uint32_t b0, uint32_t b1) {
    asm volatile("mma.sync.aligned.m16n8k16.row.col.f32.bf16.bf16.f32 "
                 "{%0,%1,%2,%3}, {%4,%5,%6,%7}, {%8,%9}, {%0,%1,%2,%3};"
                 : "+f"(c[0]), "+f"(c[1]), "+f"(c[2]), "+f"(c[3])
                 : "r"(a[0]), "r"(a[1]), "r"(a[2]), "r"(a[3]), "r"(b0), "r"(b1));
}
__device__ __forceinline__ uint32_t bf2pack(float x, float y) {
    __nv_bfloat162 p = {__float2bfloat16(x), __float2bfloat16(y)};
    return *(uint32_t*)&p;
}

#define SWZ(x) ((x) ^ (((x) >> 3) & 0x70))
// 256-byte-row swizzle: off(r, colbyte) = r*256 + (colbyte ^ ((r&7)*16))
#define SWZ256(r, cb) ((r) * 256 + ((cb) ^ (((r) & 7) * 16)))

// ---------------------------------------------------------------------------
// Big HMMA GEMM with fused weight-GEMM epilogue.
//   main:  T[row, d] = sum_k A[row,k] * (Bh[d,k] + Bl[d,k])      (k = KT dim)
//   epi:   C2[row, j] = sum_d T[row,d] * (Wh[j,d] + Wl[j,d])
//   optionally also writes T itself to C (WRITEC).
// TRANSA=false: A bf16 [rows, KT] row-major per batch (k contiguous)
// TRANSA=true:  A bf16 [KT, rows] per batch (row contiguous) -> ldmatrix.trans
// grid (rows/128, 1, BB), 256 threads, 3-stage cp.async pipeline.
// ---------------------------------------------------------------------------
template<int KT, bool TRANSA, bool WRITEC>
__global__ __launch_bounds__(256)
void mma_big(const __nv_bfloat16* __restrict__ A,
             const __nv_bfloat16* __restrict__ Bh, const __nv_bfloat16* __restrict__ Bl,
             const __nv_bfloat16* __restrict__ Wh, const __nv_bfloat16* __restrict__ Wl,
             float* __restrict__ C, float* __restrict__ C2, int rows) {
    constexpr int S  = KT / 64;          // K stages (64 k per stage)
    constexpr int NT = 3;                // tiles per stage (A, Bh, Bl)
    constexpr int TILEB = 128 * 128;     // 16 KB per tile
    constexpr int NBUF = 3;              // pipeline depth

    extern __shared__ __align__(1024) uint8_t smem_raw[];
    const uint32_t sb = (smem_u32(smem_raw) + 1023u) & ~1023u;

    const int tid = threadIdx.x;
    const int wid = tid >> 5, lane = tid & 31;
    const int wrow = wid >> 2;           // 0..1  (64 output rows each)
    const int wcol = wid & 3;            // 0..3  (32 d cols each)
    const int b = blockIdx.z;
    const int row0 = blockIdx.x * 128;

    const char* GA;
    size_t strideA;
    if (TRANSA) {   // A[k, row] per batch, row contiguous
        GA = (const char*)(A + (size_t)b * KT * rows) + (size_t)row0 * 2;
        strideA = (size_t)rows * 2;
    } else {        // A[row, k] per batch, k contiguous
        GA = (const char*)(A + ((size_t)b * rows + row0) * KT);
        strideA = (size_t)KT * 2;
    }
    const char* GBh = (const char*)(Bh + (size_t)b * 128 * KT);
    const char* GBl = (const char*)(Bl + (size_t)b * 128 * KT);

    auto load_stage = [&](int s) {
        const uint32_t tb = sb + (uint32_t)(s % NBUF) * NT * TILEB;
        if (TRANSA) {
            // tile: [64 k-rows x 256 B (128 row-cols)]
            const char* ga = GA + (size_t)s * 64 * strideA;
#pragma unroll
            for (int i = 0; i < 4; i++) {
                int c = tid + i * 256;           // 0..1023
                int r = c >> 4, ch = c & 15;
                cp16(tb + SWZ256(r, ch * 16), ga + (size_t)r * strideA + ch * 16);
            }
        } else {
            // tile: [128 rows x 128 B (64 k)]
            const char* ga = GA + (size_t)s * 128;
#pragma unroll
            for (int i = 0; i < 4; i++) {
                int c = tid + i * 256;
                int r = c >> 3, ch = c & 7;
                cp16(tb + SWZ(r * 128 + ch * 16), ga + (size_t)r * strideA + ch * 16);
            }
        }
        const size_t gk = (size_t)s * 128;
#pragma unroll
        for (int t = 0; t < 2; t++) {
            const char* gt = (t ? GBl : GBh) + gk;
            const uint32_t st = tb + (1 + t) * TILEB;
#pragma unroll
            for (int i = 0; i < 4; i++) {
                int c = tid + i * 256;
                int r = c >> 3, ch = c & 7;
                cp16(st + SWZ(r * 128 + ch * 16), gt + (size_t)r * (KT * 2) + ch * 16);
            }
        }
        cp_commit();
    };

    float acc[4][4][4];
#pragma unroll
    for (int mi = 0; mi < 4; mi++)
#pragma unroll
        for (int nj = 0; nj < 4; nj++)
#pragma unroll
            for (int q = 0; q < 4; q++) acc[mi][nj][q] = 0.0f;

    load_stage(0);
    load_stage(1);

    const int lr = lane & 15;            // ldmatrix row within 16
    const int lc = (lane >> 4) * 16;     // ldmatrix byte col (0 or 16)

    for (int s = 0; s < S; s++) {
        if (s + 2 < S)      { load_stage(s + 2); cp_wait<2>(); }
        else if (s + 1 < S) { cp_wait<1>(); }
        else                { cp_wait<0>(); }
        __syncthreads();

        const uint32_t tb = sb + (uint32_t)(s % NBUF) * NT * TILEB;

#pragma unroll
        for (int ks = 0; ks < 4; ks++) {
            const int kb = ks * 32;
            uint32_t a[4][4];
            if (TRANSA) {
                // logical A[row=e, k=m]; physical [64 m x 128 e(256B)]
                const int mrow = ks * 16 + (lane & 7) + ((lane >> 4) & 1) * 8;
                const int cb0  = wrow * 128 + ((lane >> 3) & 1) * 16;
#pragma unroll
                for (int mi = 0; mi < 4; mi++)
                    ldsm4t(a[mi], tb + SWZ256(mrow, cb0 + mi * 32));
            } else {
#pragma unroll
                for (int mi = 0; mi < 4; mi++)
                    ldsm4(a[mi], tb + SWZ((wrow * 64 + mi * 16 + lr) * 128 + kb + lc));
            }
#pragma unroll
            for (int h = 0; h < 2; h++) {
                const uint32_t Bt = tb + (1 + h) * TILEB;
                uint32_t bb[2][4];
#pragma unroll
                for (int n2 = 0; n2 < 2; n2++)
                    ldsm4(bb[n2], Bt + SWZ((wcol * 32 + n2 * 16 + lr) * 128 + kb + lc));
#pragma unroll
                for (int mi = 0; mi < 4; mi++)
#pragma unroll
                    for (int nj = 0; nj < 4; nj++) {
                        uint32_t b0 = bb[nj >> 1][nj & 1];
                        uint32_t b1 = bb[nj >> 1][2 + (nj & 1)];
                        hmma(acc[mi][nj], a[mi], b0, b1);
                    }
            }
        }
        __syncthreads();
    }

    // =====================================================================
    // Fused epilogue: C2 = acc @ W^T (hi/lo), optional C = acc.
    // smem: accH @ sb+0 (32K), accL @ +32K, WH @ +64K, WL @ +96K
    // acc/W tiles: [128 rows x 128 cols bf16] = 256-B rows, SWZ256 layout.
    // =====================================================================
    const uint32_t sAH = sb, sAL = sb + 32768, sWH = sb + 65536, sWL = sb + 98304;

    // prefetch W hi/lo
#pragma unroll
    for (int t = 0; t < 2; t++) {
        const char* gw = (const char*)(t ? Wl : Wh);
        const uint32_t st = t ? sWL : sWH;
#pragma unroll
        for (int i = 0; i < 8; i++) {
            int c = tid + i * 256;               // 0..2047
            int r = c >> 4, ch = c & 15;
            cp16(st + SWZ256(r, ch * 16), gw + (size_t)r * 256 + ch * 16);
        }
    }
    cp_commit();

    // split acc -> smem bf16 hi/lo
    const int gr = lane >> 2, tc = lane & 3;
#pragma unroll
    for (int mi = 0; mi < 4; mi++)
#pragma unroll
        for (int nj = 0; nj < 4; nj++) {
            const int cb = (wcol * 32 + nj * 8 + tc * 2) * 2;
#pragma unroll
            for (int h = 0; h < 2; h++) {
                const int e = wrow * 64 + mi * 16 + gr + h * 8;
                float v0 = acc[mi][nj][h * 2 + 0];
                float v1 = acc[mi][nj][h * 2 + 1];
                __nv_bfloat16 h0 = __float2bfloat16(v0);
                __nv_bfloat16 h1 = __float2bfloat16(v1);
                float l0f = v0 - __bfloat162float(h0);
                float l1f = v1 - __bfloat162float(h1);
                __nv_bfloat162 hp = {h0, h1};
                __nv_bfloat162 lp = {__float2bfloat16(l0f), __float2bfloat16(l1f)};
                const uint32_t off = SWZ256(e, cb);
                sts32(sAH + off, *(uint32_t*)&hp);
                sts32(sAL + off, *(uint32_t*)&lp);
            }
        }

    if (WRITEC) {
        float* Cw = C + ((size_t)b * rows + row0 + wrow * 64) * 128 + wcol * 32;
#pragma unroll
        for (int mi = 0; mi < 4; mi++)
#pragma unroll
            for (int nj = 0; nj < 4; nj++) {
                float* p0 = Cw + (mi * 16 + gr) * 128 + nj * 8 + tc * 2;
                float* p1 = p0 + 8 * 128;
                *(float2*)p0 = make_float2(acc[mi][nj][0], acc[mi][nj][1]);
                *(float2*)p1 = make_float2(acc[mi][nj][2], acc[mi][nj][3]);
            }
    }

    cp_wait<0>();
    __syncthreads();

    float out2[4][4][4];
#pragma unroll
    for (int mi = 0; mi < 4; mi++)
#pragma unroll
        for (int nj = 0; nj < 4; nj++)
#pragma unroll
            for (int q = 0; q < 4; q++) out2[mi][nj][q] = 0.0f;

#pragma unroll
    for (int ks = 0; ks < 8; ks++) {
        const int kb = ks * 32;
        uint32_t aH[4][4], aL[4][4];
#pragma unroll
        for (int mi = 0; mi < 4; mi++) {
            const int e = wrow * 64 + mi * 16 + lr;
            const uint32_t off = SWZ256(e, kb + lc);
            ldsm4(aH[mi], sAH + off);
            ldsm4(aL[mi], sAL + off);
        }
        uint32_t bH[2][4], bL[2][4];
#pragma unroll
        for (int n2 = 0; n2 < 2; n2++) {
            const int r = wcol * 32 + n2 * 16 + lr;
            const uint32_t off = SWZ256(r, kb + lc);
            ldsm4(bH[n2], sWH + off);
            ldsm4(bL[n2], sWL + off);
        }
#pragma unroll
        for (int mi = 0; mi < 4; mi++)
#pragma unroll
            for (int nj = 0; nj < 4; nj++) {
                uint32_t bh0 = bH[nj >> 1][nj & 1], bh1 = bH[nj >> 1][2 + (nj & 1)];
                uint32_t bl0 = bL[nj >> 1][nj & 1], bl1 = bL[nj >> 1][2 + (nj & 1)];
                hmma(out2[mi][nj], aH[mi], bh0, bh1);
                hmma(out2[mi][nj], aH[mi], bl0, bl1);
                hmma(out2[mi][nj], aL[mi], bh0, bh1);
            }
    }

    float* C2w = C2 + ((size_t)b * rows + row0 + wrow * 64) * 128 + wcol * 32;
#pragma unroll
    for (int mi = 0; mi < 4; mi++)
#pragma unroll
        for (int nj = 0; nj < 4; nj++) {
            float* p0 = C2w + (mi * 16 + gr) * 128 + nj * 8 + tc * 2;
            float* p1 = p0 + 8 * 128;
            *(float2*)p0 = make_float2(out2[mi][nj][0], out2[mi][nj][1]);
            *(float2*)p1 = make_float2(out2[mi][nj][2], out2[mi][nj][3]);
        }
}

// ---------------------------------------------------------------------------
// inc fp32 [B,M,E] -> bf16 [B,M,E] (pure streaming)
// ---------------------------------------------------------------------------
__global__ __launch_bounds__(256)
void conv_inc(const float* __restrict__ inc, __nv_bfloat16* __restrict__ incN) {
    const size_t i = ((size_t)blockIdx.x * 256 + threadIdx.x) * 8;
    float4 v0 = *(const float4*)(inc + i);
    float4 v1 = *(const float4*)(inc + i + 4);
    uint4 pk;
    pk.x = bf2pack(v0.x, v0.y);
    pk.y = bf2pack(v0.z, v0.w);
    pk.z = bf2pack(v1.x, v1.y);
    pk.w = bf2pack(v1.z, v1.w);
    *(uint4*)(incN + i) = pk;
}

// ---------------------------------------------------------------------------
// X fp32 [B,R,128] -> transposed hi/lo bf16 [B,128,R]
// ---------------------------------------------------------------------------
__global__ __launch_bounds__(256)
void conv_hiloT(const float* __restrict__ X, __nv_bfloat16* __restrict__ Th,
                __nv_bfloat16* __restrict__ Tl, int R) {
    __shared__ float t[64][129];
    const int b = blockIdx.y;
    const int r0 = blockIdx.x * 64;
    const float* Xb = X + ((size_t)b * R + r0) * 128;
    const int tid = threadIdx.x;

#pragma unroll
    for (int i = 0; i < 8; i++) {
        int q = tid + i * 256;
        int r = q >> 5, c4 = q & 31;
        float4 v = *(const float4*)(Xb + (size_t)r * 128 + c4 * 4);
        t[r][c4 * 4 + 0] = v.x; t[r][c4 * 4 + 1] = v.y;
        t[r][c4 * 4 + 2] = v.z; t[r][c4 * 4 + 3] = v.w;
    }
    __syncthreads();
#pragma unroll
    for (int i = 0; i < 8; i++) {
        int q = tid + i * 256;
        int d = q >> 4, m4 = q & 15;
        __nv_bfloat16 hi[4], lo[4];
#pragma unroll
        for (int j = 0; j < 4; j++) {
            float v = t[m4 * 4 + j][d];
            hi[j] = __float2bfloat16(v);
            lo[j] = __float2bfloat16(v - __bfloat162float(hi[j]));
        }
        size_t off = ((size_t)b * 128 + d) * R + r0 + m4 * 4;
        __nv_bfloat162 h0 = {hi[0], hi[1]}, h1 = {hi[2], hi[3]};
        __nv_bfloat162 l0 = {lo[0], lo[1]}, l1 = {lo[2], lo[3]};
        uint2 ph = {*(uint32_t*)&h0, *(uint32_t*)&h1};
        uint2 pl = {*(uint32_t*)&l0, *(uint32_t*)&l1};
        *(uint2*)(Th + off) = ph;
        *(uint2*)(Tl + off) = pl;
    }
}

// ---------------------------------------------------------------------------
// Weight hi/lo converter: two 128x128 fp32 row-major -> bf16 hi/lo
// grid (64, 2)
// ---------------------------------------------------------------------------
__global__ __launch_bounds__(256)
void conv_w2(const float* __restrict__ Wa, const float* __restrict__ Wp,
             __nv_bfloat16* __restrict__ WaH, __nv_bfloat16* __restrict__ WaL,
             __nv_bfloat16* __restrict__ WpH, __nv_bfloat16* __restrict__ WpL) {
    const int i = blockIdx.x * 256 + threadIdx.x;   // 0..16383
    const float* src = blockIdx.y ? Wp : Wa;
    __nv_bfloat16* dh = blockIdx.y ? WpH : WaH;
    __nv_bfloat16* dl = blockIdx.y ? WpL : WaL;
    float v = src[i];
    __nv_bfloat16 h = __float2bfloat16(v);
    dh[i] = h;
    dl[i] = __float2bfloat16(v - __bfloat162float(h));
}

// ---------------------------------------------------------------------------
// FFMA GEMM (64x128 tile, 128 threads): C[r, j] = sum_k X[r,k] * W[j,k]
// with fused transposed hi/lo bf16 output [B,128,Rb].
// ---------------------------------------------------------------------------
__global__ __launch_bounds__(128)
void gemm_xwt(const float* __restrict__ X, const float* __restrict__ W,
              float* __restrict__ C, __nv_bfloat16* __restrict__ Th,
              __nv_bfloat16* __restrict__ Tl, int Rb) {
    __shared__ float As[16][64];
    __shared__ float Bs[16][128];
    const int tid = threadIdx.x;
    const int tx = tid & 15, ty = tid >> 4;
    const size_t r0 = (size_t)blockIdx.x * 64;

    float acc[8][8];
#pragma unroll
    for (int i = 0; i < 8; i++)
#pragma unroll
        for (int j = 0; j < 8; j++) acc[i][j] = 0.0f;

    for (int k0 = 0; k0 < 128; k0 += 16) {
        // X tile: 64 rows x 16 k
#pragma unroll
        for (int l = 0; l < 2; l++) {
            int q = tid * 2 + l;             // 0..255
            int row = q >> 2, kq = q & 3;
            float4 va = *(const float4*)(X + (r0 + row) * 128 + k0 + kq * 4);
            As[kq * 4 + 0][row] = va.x; As[kq * 4 + 1][row] = va.y;
            As[kq * 4 + 2][row] = va.z; As[kq * 4 + 3][row] = va.w;
        }
        // W tile: 128 rows x 16 k
#pragma unroll
        for (int l = 0; l < 4; l++) {
            float4 vb = *(const float4*)(W + (size_t)tid * 128 + k0 + l * 4);
            Bs[l * 4 + 0][tid] = vb.x; Bs[l * 4 + 1][tid] = vb.y;
            Bs[l * 4 + 2][tid] = vb.z; Bs[l * 4 + 3][tid] = vb.w;
        }
        __syncthreads();
#pragma unroll
        for (int k = 0; k < 16; k++) {
            float a[8], bv[8];
            *(float4*)(a)      = *(const float4*)&As[k][ty * 8];
            *(float4*)(a + 4)  = *(const float4*)&As[k][ty * 8 + 4];
            *(float4*)(bv)     = *(const float4*)&Bs[k][tx * 8];
            *(float4*)(bv + 4) = *(const float4*)&Bs[k][tx * 8 + 4];
#pragma unroll
            for (int i = 0; i < 8; i++)
#pragma unroll
                for (int j = 0; j < 8; j++)
                    acc[i][j] = fmaf(a[i], bv[j], acc[i][j]);
        }
        __syncthreads();
    }
#pragma unroll
    for (int i = 0; i < 8; i++) {
        float* crow = C + (r0 + (size_t)(ty * 8 + i)) * 128 + tx * 8;
        *(float4*)crow       = make_float4(acc[i][0], acc[i][1], acc[i][2], acc[i][3]);
        *(float4*)(crow + 4) = make_float4(acc[i][4], acc[i][5], acc[i][6], acc[i][7]);
    }
    // fused transposed hi/lo bf16 output
    const int b  = (int)(r0 / Rb);
    const int e0 = (int)(r0 % Rb) + ty * 8;
#pragma unroll
    for (int j = 0; j < 8; j++) {
        const int d = tx * 8 + j;
        __nv_bfloat16 hi[8], lo[8];
#pragma unroll
        for (int i = 0; i < 8; i++) {
            float v = acc[i][j];
            hi[i] = __float2bfloat16(v);
            lo[i] = __float2bfloat16(v - __bfloat162float(hi[i]));
        }
        size_t off = ((size_t)b * 128 + d) * Rb + e0;
        *(uint4*)(Th + off) = *(uint4*)hi;
        *(uint4*)(Tl + off) = *(uint4*)lo;
    }
}

// ---------------------------------------------------------------------------
// pre[b,e,d] = agg[b,e,d] * softmax over e of eatt[b,:,d]
// ---------------------------------------------------------------------------
__global__ __launch_bounds__(256)
void softmax_mul(const float* __restrict__ eatt, const float* __restrict__ agg,
                 float* __restrict__ pre) {
    const int b = blockIdx.y;
    const int d = blockIdx.x * 32 + threadIdx.x;
    const int ey = threadIdx.y;
    const float* Eb = eatt + (size_t)b * EE * DD;
    const float* Ab = agg  + (size_t)b * EE * DD;
    float* Pb = pre + (size_t)b * EE * DD;

    __shared__ float rmax[8][32];
    __shared__ float rsum[8][32];

    float mx = -3.0e38f;
    for (int e = ey; e < EE; e += 8)
        mx = fmaxf(mx, Eb[(size_t)e * DD + d]);
    rmax[ey][threadIdx.x] = mx;
    __syncthreads();
    float m = rmax[0][threadIdx.x];
#pragma unroll
    for (int i = 1; i < 8; i++) m = fmaxf(m, rmax[i][threadIdx.x]);

    float s = 0.0f;
    for (int e = ey; e < EE; e += 8)
        s += expf(Eb[(size_t)e * DD + d] - m);
    rsum[ey][threadIdx.x] = s;
    __syncthreads();
    float sum = 0.0f;
#pragma unroll
    for (int i = 0; i < 8; i++) sum += rsum[i][threadIdx.x];
    const float inv = 1.0f / sum;

    for (int e = ey; e < EE; e += 8) {
        size_t idx = (size_t)e * DD + d;
        Pb[idx] = Ab[idx] * expf(Eb[idx] - m) * inv;
    }
}

// ---------------------------------------------------------------------------
// Launch.
// Identities: n_layers recurrence is a fixed point -> one pass; ec_Wa dead;
//   eatt = (inc^T @ feat) @ Wa^T = agg @ Wa^T (fused into GEMM1 epilogue);
//   node = (inc @ ef) @ Wp^T (fused into GEMM2 epilogue, w never materialized).
// Precision: inc {0,1} exact in bf16; fp32 operands hi/lo bf16 split.
// ---------------------------------------------------------------------------
extern "C" void kernel_launch(void* const* d_in, const int* in_sizes, int n_in,
                              void* d_out, int out_size) {
    const float* features = (const float*)d_in[0];
    const float* inc      = (const float*)d_in[1];
    const float* vc_Wa    = (const float*)d_in[2];
    const float* vc_Wp    = (const float*)d_in[3];
    const float* ec_Wp    = (const float*)d_in[6];

    float* out_node = (float*)d_out;                 // [B,M,D]
    float* out_edge = out_node + NODE_ELEMS;         // [B,E,D]

    float *p_eatt, *p_agg, *p_pre;
    __nv_bfloat16 *p_incN, *p_featTh, *p_featTl, *p_efTh, *p_efTl;
    __nv_bfloat16 *p_WaH, *p_WaL, *p_WpH, *p_WpL;
    cudaGetSymbolAddress((void**)&p_eatt,   g_eatt);
    cudaGetSymbolAddress((void**)&p_agg,    g_agg);
    cudaGetSymbolAddress((void**)&p_pre,    g_pre);
    cudaGetSymbolAddress((void**)&p_incN,   g_inc_bf);
    cudaGetSymbolAddress((void**)&p_featTh, g_featT_hi);
    cudaGetSymbolAddress((void**)&p_featTl, g_featT_lo);
    cudaGetSymbolAddress((void**)&p_efTh,   g_efT_hi);
    cudaGetSymbolAddress((void**)&p_efTl,   g_efT_lo);
    cudaGetSymbolAddress((void**)&p_WaH,    g_WaH);
    cudaGetSymbolAddress((void**)&p_WaL,    g_WaL);
    cudaGetSymbolAddress((void**)&p_WpH,    g_WpH);
    cudaGetSymbolAddress((void**)&p_WpL,    g_WpL);

    const int SMEM = 3 * 3 * 16384 + 1024;   // 148480 (main loop; epi uses 128K)
    cudaFuncSetAttribute(mma_big<MM, true,  true >,
                         cudaFuncAttributeMaxDynamicSharedMemorySize, SMEM);
    cudaFuncSetAttribute(mma_big<EE, false, false>,
                         cudaFuncAttributeMaxDynamicSharedMemorySize, SMEM);

    // 1. inc -> bf16 [B,M,E] (streaming)
    conv_inc<<<(int)(((size_t)BB * MM * EE) / 2048), 256>>>(inc, p_incN);

    // 2. feat -> transposed hi/lo bf16 [B,128,M]
    conv_hiloT<<<dim3(MM / 64, BB), 256>>>(features, p_featTh, p_featTl, MM);

    // 3. weights -> hi/lo bf16
    conv_w2<<<dim3(64, 2), 256>>>(vc_Wa, ec_Wp, p_WaH, p_WaL, p_WpH, p_WpL);

    // 4. agg = inc^T @ feat  (+ fused eatt = agg @ Wa^T)
    mma_big<MM, true, true><<<dim3(EE / 128, 1, BB), 256, SMEM>>>(
        p_incN, p_featTh, p_featTl, p_WaH, p_WaL, p_agg, p_eatt, EE);

    // 5. pre = agg * softmax_e(eatt)
    softmax_mul<<<dim3(DD / 32, BB), dim3(32, 8)>>>(p_eatt, p_agg, p_pre);

    // 6. ef = pre @ vc_Wp^T -> edge output + fused efT hi/lo
    gemm_xwt<<<(BB * EE) / 64, 128>>>(p_pre, vc_Wp, out_edge, p_efTh, p_efTl, EE);

    // 7. node = (inc @ ef) @ ec_Wp^T  (w stays in registers/smem)
    mma_big<EE, false, false><<<dim3(MM / 128, 1, BB), 256, SMEM>>>(
        p_incN, p_efTh, p_efTl, p_WpH, p_WpL, nullptr, out_node, MM);
}